// round 1
// baseline (speedup 1.0000x reference)
#include <cuda_runtime.h>
#include <cstddef>

#define HID 512
#define EDIM 64
#define BN_EPS 1e-5f
#define MAXN 50000
#define MAXE 400000

// Scratch (device globals; allocation in kernel_launch is forbidden)
__device__ float g_aggr[MAXN * HID];            // 102.4 MB
__device__ float g_h1[MAXN * 2 * HID];          // 204.8 MB
__device__ float g_h2[MAXN * HID];              // 102.4 MB
__device__ float g_stats1[4 * HID];             // sums[1024], sumsq[1024]
__device__ float g_stats2[2 * HID];             // sums[512], sumsq[512]
__device__ float g_bnp1[4 * HID];               // scale[1024], shift[1024]
__device__ float g_bnp2[2 * HID];               // scale[512], shift[512]

// ---------------------------------------------------------------------------
__global__ void zero_kernel(float* __restrict__ p, int n) {
    int i = blockIdx.x * blockDim.x + threadIdx.x;
    int stride = gridDim.x * blockDim.x;
    for (; i < n; i += stride) p[i] = 0.0f;
}

// ---------------------------------------------------------------------------
// Fused edge kernel: aggr[dst] += relu(x[src] + edge_attr @ W_e + b_e)
// Block: 512 threads = 4 groups of 128; each group handles 8 edges per tile,
// each thread owns 4 consecutive output columns (float4). W_e cached in smem.
__global__ void __launch_bounds__(512) edge_kernel(
    const float* __restrict__ x, const float* __restrict__ ea,
    const int* __restrict__ src, const int* __restrict__ dst,
    const float* __restrict__ We, const float* __restrict__ be,
    float* __restrict__ aggr, int E)
{
    extern __shared__ float smem[];
    float* sWe = smem;                 // 64*512 floats = 128 KB
    float* sEa = smem + EDIM * HID;    // 32*64 floats  =   8 KB

    int t = threadIdx.x;
    // stage W_e
    for (int i = t; i < EDIM * HID / 4; i += 512) {
        reinterpret_cast<float4*>(sWe)[i] = reinterpret_cast<const float4*>(We)[i];
    }
    int g  = t >> 7;      // edge-group 0..3
    int lc = t & 127;     // column-quad: columns lc*4 .. lc*4+3
    float4 bev = reinterpret_cast<const float4*>(be)[lc];

    int numTiles = (E + 31) / 32;
    for (int tile = blockIdx.x; tile < numTiles; tile += gridDim.x) {
        int e0 = tile * 32;
        __syncthreads();   // protect sEa reuse (also orders sWe on first iter)
        {
            // 32 edges * 64 attrs = 2048 floats = 512 float4, one per thread
            float4 v = make_float4(0.f, 0.f, 0.f, 0.f);
            long long goff = (long long)e0 * EDIM + t * 4;
            if (goff < (long long)E * EDIM)
                v = reinterpret_cast<const float4*>(ea)[e0 * (EDIM / 4) + t];
            reinterpret_cast<float4*>(sEa)[t] = v;
        }
        __syncthreads();

        float acc[8][4];
        #pragma unroll
        for (int e = 0; e < 8; e++) { acc[e][0]=0.f; acc[e][1]=0.f; acc[e][2]=0.f; acc[e][3]=0.f; }

        const float* myEa = sEa + (g * 8) * EDIM;
        #pragma unroll 8
        for (int k = 0; k < EDIM; k++) {
            float4 w = reinterpret_cast<const float4*>(sWe)[k * (HID / 4) + lc];
            #pragma unroll
            for (int e = 0; e < 8; e++) {
                float a = myEa[e * EDIM + k];
                acc[e][0] += a * w.x; acc[e][1] += a * w.y;
                acc[e][2] += a * w.z; acc[e][3] += a * w.w;
            }
        }

        #pragma unroll
        for (int e = 0; e < 8; e++) {
            int eg = e0 + g * 8 + e;
            if (eg < E) {
                int s = __ldg(&src[eg]);
                int d = __ldg(&dst[eg]);
                float4 xv = reinterpret_cast<const float4*>(x)[(size_t)s * (HID / 4) + lc];
                float r0 = fmaxf(acc[e][0] + bev.x + xv.x, 0.f);
                float r1 = fmaxf(acc[e][1] + bev.y + xv.y, 0.f);
                float r2 = fmaxf(acc[e][2] + bev.z + xv.z, 0.f);
                float r3 = fmaxf(acc[e][3] + bev.w + xv.w, 0.f);
                float* ap = aggr + (size_t)d * HID + lc * 4;
                atomicAdd(ap + 0, r0);
                atomicAdd(ap + 1, r1);
                atomicAdd(ap + 2, r2);
                atomicAdd(ap + 3, r3);
            }
        }
    }
}

// ---------------------------------------------------------------------------
// Tiled fp32 GEMM: C[M,NC] = A[M,K] @ B[K,NC] + bias, with
//  - optional prologue: A_eff = (1+eps)*A + A2 (GIN combine, fused)
//  - epilogue: per-column sum and sum-of-squares accumulated into stats[2*NC]
// BM=BN=128, BK=16, 256 threads, 8x8 microtile.
template <bool COMBINE>
__global__ void __launch_bounds__(256) gemm_kernel(
    const float* __restrict__ A, const float* __restrict__ A2,
    const float* __restrict__ B, const float* __restrict__ bias,
    float* __restrict__ C, float* __restrict__ stats,
    int M, int K, int NC, const float* __restrict__ epsp)
{
    __shared__ float As[16][132];
    __shared__ float Bs[16][128];
    __shared__ float sSum[128];
    __shared__ float sSq[128];

    int t = threadIdx.x;
    int warp = t >> 5, lane = t & 31;
    int tr = ((warp >> 1) << 2) + (lane >> 3);   // 0..15 (row group)
    int tc = ((warp & 1) << 3) + (lane & 7);     // 0..15 (col group)
    int bm = blockIdx.y * 128;
    int bn = blockIdx.x * 128;

    float c1 = 1.0f;
    if (COMBINE) c1 = 1.0f + __ldg(epsp);

    float acc[8][8];
    #pragma unroll
    for (int i = 0; i < 8; i++)
        #pragma unroll
        for (int j = 0; j < 8; j++) acc[i][j] = 0.0f;

    for (int kt = 0; kt < K; kt += 16) {
        // A tile 128x16 (512 float4, 2 per thread), stored transposed
        #pragma unroll
        for (int i = 0; i < 2; i++) {
            int idx = t + (i << 8);
            int row = idx >> 2;
            int col = (idx & 3) << 2;
            int gm = bm + row;
            float4 v = make_float4(0.f, 0.f, 0.f, 0.f);
            if (gm < M) {
                size_t off = ((size_t)gm * K + kt + col) >> 2;
                v = reinterpret_cast<const float4*>(A)[off];
                if (COMBINE) {
                    float4 u = reinterpret_cast<const float4*>(A2)[off];
                    v.x = c1 * v.x + u.x; v.y = c1 * v.y + u.y;
                    v.z = c1 * v.z + u.z; v.w = c1 * v.w + u.w;
                }
            }
            As[col + 0][row] = v.x; As[col + 1][row] = v.y;
            As[col + 2][row] = v.z; As[col + 3][row] = v.w;
        }
        // B tile 16x128 (512 float4, 2 per thread)
        #pragma unroll
        for (int i = 0; i < 2; i++) {
            int idx = t + (i << 8);
            int row = idx >> 5;
            int c4  = idx & 31;
            float4 v = reinterpret_cast<const float4*>(B)[((size_t)(kt + row) * NC + bn) / 4 + c4];
            *reinterpret_cast<float4*>(&Bs[row][c4 << 2]) = v;
        }
        __syncthreads();

        #pragma unroll
        for (int k = 0; k < 16; k++) {
            float a[8], b[8];
            float4 a0 = *reinterpret_cast<const float4*>(&As[k][tr * 8]);
            float4 a1 = *reinterpret_cast<const float4*>(&As[k][tr * 8 + 4]);
            float4 b0 = *reinterpret_cast<const float4*>(&Bs[k][tc * 8]);
            float4 b1 = *reinterpret_cast<const float4*>(&Bs[k][tc * 8 + 4]);
            a[0]=a0.x; a[1]=a0.y; a[2]=a0.z; a[3]=a0.w;
            a[4]=a1.x; a[5]=a1.y; a[6]=a1.z; a[7]=a1.w;
            b[0]=b0.x; b[1]=b0.y; b[2]=b0.z; b[3]=b0.w;
            b[4]=b1.x; b[5]=b1.y; b[6]=b1.z; b[7]=b1.w;
            #pragma unroll
            for (int i = 0; i < 8; i++)
                #pragma unroll
                for (int j = 0; j < 8; j++)
                    acc[i][j] += a[i] * b[j];
        }
        __syncthreads();
    }

    // Epilogue: bias add, store, column stats
    if (t < 128) { sSum[t] = 0.0f; sSq[t] = 0.0f; }
    __syncthreads();

    float bv[8];
    #pragma unroll
    for (int j = 0; j < 8; j++) bv[j] = __ldg(&bias[bn + tc * 8 + j]);

    float ls[8], lq[8];
    #pragma unroll
    for (int j = 0; j < 8; j++) { ls[j] = 0.0f; lq[j] = 0.0f; }

    #pragma unroll
    for (int i = 0; i < 8; i++) {
        int gm = bm + tr * 8 + i;
        if (gm < M) {
            float out[8];
            #pragma unroll
            for (int j = 0; j < 8; j++) {
                float v = acc[i][j] + bv[j];
                out[j] = v;
                ls[j] += v; lq[j] += v * v;
            }
            float4* cp = reinterpret_cast<float4*>(C + (size_t)gm * NC + bn + tc * 8);
            cp[0] = make_float4(out[0], out[1], out[2], out[3]);
            cp[1] = make_float4(out[4], out[5], out[6], out[7]);
        }
    }
    #pragma unroll
    for (int j = 0; j < 8; j++) {
        atomicAdd(&sSum[tc * 8 + j], ls[j]);
        atomicAdd(&sSq[tc * 8 + j], lq[j]);
    }
    __syncthreads();
    if (t < 128) {
        atomicAdd(&stats[bn + t],       sSum[t]);
        atomicAdd(&stats[NC + bn + t],  sSq[t]);
    }
}

// ---------------------------------------------------------------------------
__global__ void bnfin_kernel(const float* __restrict__ stats,
                             const float* __restrict__ g, const float* __restrict__ beta,
                             float* __restrict__ bnp, int NC, float invN)
{
    int c = blockIdx.x * blockDim.x + threadIdx.x;
    if (c < NC) {
        float mu   = stats[c] * invN;
        float var  = stats[NC + c] * invN - mu * mu;
        float rstd = rsqrtf(var + BN_EPS);
        float sc   = g[c] * rstd;
        bnp[c]      = sc;
        bnp[NC + c] = beta[c] - mu * sc;
    }
}

// out[i] = silu(in[i]*scale[col] + shift[col]); operates on float4 granularity.
__global__ void bnsilu_kernel(const float* __restrict__ in, float* __restrict__ out,
                              const float* __restrict__ bnp, int c4mask, int nc4, size_t n4)
{
    size_t i = (size_t)blockIdx.x * blockDim.x + threadIdx.x;
    size_t stride = (size_t)gridDim.x * blockDim.x;
    for (; i < n4; i += stride) {
        int c4 = (int)(i & (size_t)c4mask);
        float4 v  = reinterpret_cast<const float4*>(in)[i];
        float4 sc = reinterpret_cast<const float4*>(bnp)[c4];
        float4 sh = reinterpret_cast<const float4*>(bnp)[nc4 + c4];
        float y0 = v.x * sc.x + sh.x;
        float y1 = v.y * sc.y + sh.y;
        float y2 = v.z * sc.z + sh.z;
        float y3 = v.w * sc.w + sh.w;
        float4 r;
        r.x = y0 / (1.0f + __expf(-y0));
        r.y = y1 / (1.0f + __expf(-y1));
        r.z = y2 / (1.0f + __expf(-y2));
        r.w = y3 / (1.0f + __expf(-y3));
        reinterpret_cast<float4*>(out)[i] = r;
    }
}

// ---------------------------------------------------------------------------
extern "C" void kernel_launch(void* const* d_in, const int* in_sizes, int n_in,
                              void* d_out, int out_size)
{
    const float* x     = (const float*)d_in[0];
    const float* ea    = (const float*)d_in[1];
    const int*   ei    = (const int*)d_in[2];
    const float* We    = (const float*)d_in[3];
    const float* be    = (const float*)d_in[4];
    const float* W1    = (const float*)d_in[5];
    const float* b1    = (const float*)d_in[6];
    const float* g1    = (const float*)d_in[7];
    const float* beta1 = (const float*)d_in[8];
    const float* W2    = (const float*)d_in[9];
    const float* b2    = (const float*)d_in[10];
    const float* g2    = (const float*)d_in[11];
    const float* beta2 = (const float*)d_in[12];
    const float* epsp  = (const float*)d_in[13];

    int N = in_sizes[0] / HID;
    int E = in_sizes[1] / EDIM;
    const int* src = ei;
    const int* dst = ei + E;

    float *aggr, *h1, *h2, *stats1, *stats2, *bnp1, *bnp2;
    cudaGetSymbolAddress((void**)&aggr,   g_aggr);
    cudaGetSymbolAddress((void**)&h1,     g_h1);
    cudaGetSymbolAddress((void**)&h2,     g_h2);
    cudaGetSymbolAddress((void**)&stats1, g_stats1);
    cudaGetSymbolAddress((void**)&stats2, g_stats2);
    cudaGetSymbolAddress((void**)&bnp1,   g_bnp1);
    cudaGetSymbolAddress((void**)&bnp2,   g_bnp2);

    // 1) zero scratch accumulators
    zero_kernel<<<2048, 256>>>(aggr, N * HID);
    zero_kernel<<<4, 256>>>(stats1, 4 * HID);
    zero_kernel<<<2, 256>>>(stats2, 2 * HID);

    // 2) fused edge message + scatter-add
    size_t shmem = (size_t)(EDIM * HID + 32 * EDIM) * sizeof(float);
    cudaFuncSetAttribute(edge_kernel, cudaFuncAttributeMaxDynamicSharedMemorySize, (int)shmem);
    edge_kernel<<<1184, 512, shmem>>>(x, ea, src, dst, We, be, aggr, E);

    // 3) GEMM1: h1 = ((1+eps)*x + aggr) @ W1 + b1, with col stats
    {
        dim3 grid((2 * HID) / 128, (N + 127) / 128);
        gemm_kernel<true><<<grid, 256>>>(x, aggr, W1, b1, h1, stats1, N, HID, 2 * HID, epsp);
    }
    // 4) finalize BN1 params; apply BN1 + SiLU in place on h1
    bnfin_kernel<<<(2 * HID + 255) / 256, 256>>>(stats1, g1, beta1, bnp1, 2 * HID, 1.0f / N);
    bnsilu_kernel<<<2048, 256>>>(h1, h1, bnp1, 255, 256, (size_t)N * 2 * HID / 4);

    // 5) GEMM2: h2 = h1' @ W2 + b2, with col stats
    {
        dim3 grid(HID / 128, (N + 127) / 128);
        gemm_kernel<false><<<grid, 256>>>(h1, nullptr, W2, b2, h2, stats2, N, 2 * HID, HID, epsp);
    }
    // 6) finalize BN2; final BN + SiLU into d_out
    bnfin_kernel<<<(HID + 255) / 256, 256>>>(stats2, g2, beta2, bnp2, HID, 1.0f / N);
    bnsilu_kernel<<<2048, 256>>>(h2, (float*)d_out, bnp2, 127, 128, (size_t)N * HID / 4);
}

// round 2
// speedup vs baseline: 1.1309x; 1.1309x over previous
#include <cuda_runtime.h>
#include <cstdint>
#include <cstddef>

#define HID 512
#define EDIM 64
#define BN_EPS 1e-5f
#define MAXN 50000
#define MAXE 400000

// Scratch (device globals; allocation in kernel_launch is forbidden)
__device__ float g_aggr[MAXN * HID];            // 102.4 MB
__device__ float g_h1[MAXN * 2 * HID];          // 204.8 MB
__device__ float g_h2[MAXN * HID];              // 102.4 MB
__device__ float g_stats1[4 * HID];
__device__ float g_stats2[2 * HID];
__device__ float g_bnp1[4 * HID];
__device__ float g_bnp2[2 * HID];

// ---------------------------------------------------------------------------
__global__ void zero_kernel(float* __restrict__ p, int n) {
    int i = blockIdx.x * blockDim.x + threadIdx.x;
    int stride = gridDim.x * blockDim.x;
    for (; i < n; i += stride) p[i] = 0.0f;
}

// ---------------------------------------------------------------------------
// tf32 helpers
__device__ __forceinline__ uint32_t f32_to_tf32(float x) {
    uint32_t r;
    asm("cvt.rna.tf32.f32 %0, %1;" : "=r"(r) : "f"(x));
    return r;
}
__device__ __forceinline__ void split_tf32(float x, float& hi, float& lo) {
    uint32_t h = f32_to_tf32(x);
    float hf = __uint_as_float(h);
    hi = hf;
    lo = __uint_as_float(f32_to_tf32(x - hf));
}
__device__ __forceinline__ void mma_tf32(float c[4], const uint32_t a[4], const uint32_t b[2]) {
    asm volatile(
        "mma.sync.aligned.m16n8k8.row.col.f32.tf32.tf32.f32 "
        "{%0,%1,%2,%3}, {%4,%5,%6,%7}, {%8,%9}, {%0,%1,%2,%3};\n"
        : "+f"(c[0]), "+f"(c[1]), "+f"(c[2]), "+f"(c[3])
        : "r"(a[0]), "r"(a[1]), "r"(a[2]), "r"(a[3]), "r"(b[0]), "r"(b[1]));
}

// ---------------------------------------------------------------------------
// Fused edge kernel: aggr[dst] += relu(x[src] + edge_attr @ W_e + b_e)
__global__ void __launch_bounds__(512) edge_kernel(
    const float* __restrict__ x, const float* __restrict__ ea,
    const int* __restrict__ src, const int* __restrict__ dst,
    const float* __restrict__ We, const float* __restrict__ be,
    float* __restrict__ aggr, int E)
{
    extern __shared__ float smem[];
    float* sWe = smem;                 // 64*512 floats = 128 KB
    float* sEa = smem + EDIM * HID;    // 32*64 floats  =   8 KB

    int t = threadIdx.x;
    for (int i = t; i < EDIM * HID / 4; i += 512) {
        reinterpret_cast<float4*>(sWe)[i] = reinterpret_cast<const float4*>(We)[i];
    }
    int g  = t >> 7;      // edge-group 0..3
    int lc = t & 127;     // column-quad
    float4 bev = reinterpret_cast<const float4*>(be)[lc];

    int numTiles = (E + 31) / 32;
    for (int tile = blockIdx.x; tile < numTiles; tile += gridDim.x) {
        int e0 = tile * 32;
        __syncthreads();
        {
            float4 v = make_float4(0.f, 0.f, 0.f, 0.f);
            long long goff = (long long)e0 * EDIM + t * 4;
            if (goff < (long long)E * EDIM)
                v = reinterpret_cast<const float4*>(ea)[e0 * (EDIM / 4) + t];
            reinterpret_cast<float4*>(sEa)[t] = v;
        }
        __syncthreads();

        float acc[8][4];
        #pragma unroll
        for (int e = 0; e < 8; e++) { acc[e][0]=0.f; acc[e][1]=0.f; acc[e][2]=0.f; acc[e][3]=0.f; }

        const float* myEa = sEa + (g * 8) * EDIM;
        #pragma unroll 8
        for (int k = 0; k < EDIM; k++) {
            float4 w = reinterpret_cast<const float4*>(sWe)[k * (HID / 4) + lc];
            #pragma unroll
            for (int e = 0; e < 8; e++) {
                float a = myEa[e * EDIM + k];
                acc[e][0] += a * w.x; acc[e][1] += a * w.y;
                acc[e][2] += a * w.z; acc[e][3] += a * w.w;
            }
        }

        #pragma unroll
        for (int e = 0; e < 8; e++) {
            int eg = e0 + g * 8 + e;
            if (eg < E) {
                int s = __ldg(&src[eg]);
                int d = __ldg(&dst[eg]);
                float4 xv = __ldg(reinterpret_cast<const float4*>(x) + (size_t)s * (HID / 4) + lc);
                float r0 = fmaxf(acc[e][0] + bev.x + xv.x, 0.f);
                float r1 = fmaxf(acc[e][1] + bev.y + xv.y, 0.f);
                float r2 = fmaxf(acc[e][2] + bev.z + xv.z, 0.f);
                float r3 = fmaxf(acc[e][3] + bev.w + xv.w, 0.f);
                float* ap = aggr + (size_t)d * HID + lc * 4;
                asm volatile("red.global.add.v4.f32 [%0], {%1,%2,%3,%4};"
                             :: "l"(ap), "f"(r0), "f"(r1), "f"(r2), "f"(r3) : "memory");
            }
        }
    }
}

// ---------------------------------------------------------------------------
// tf32 (3x split) tensor-core GEMM: C[M,NC] = A_eff[M,K] @ B[K,NC] + bias
// PRO==1: A_eff = (1+eps)*A + A2   (GIN combine)
// PRO==2: A_eff = silu(A*pscale[k] + pshift[k])   (fused BN1+SiLU)
// Epilogue: per-column sum & sumsq into stats[2*NC].
// Block 256 thr (8 warps, 4x2), tile 128x128x16, double-buffered smem.
template<int PRO>
__global__ void __launch_bounds__(256, 2) mma_gemm(
    const float* __restrict__ A, const float* __restrict__ A2,
    const float* __restrict__ B, const float* __restrict__ bias,
    const float* __restrict__ pscale, const float* __restrict__ pshift,
    float* __restrict__ C, float* __restrict__ stats,
    int M, int K, int NC, const float* __restrict__ epsp)
{
    const int APITCH = 20;    // 16 + 4 pad: conflict-free A frag loads
    const int BPITCH = 136;   // 128 + 8 pad: conflict-free B frag loads
    extern __shared__ float sm[];
    float* Ah = sm;                              // 2*128*20
    float* Al = Ah + 2 * 128 * APITCH;           // 2*128*20
    float* Bh = Al + 2 * 128 * APITCH;           // 2*16*136
    float* Bl = Bh + 2 * 16 * BPITCH;            // 2*16*136
    float* sSum = Bl + 2 * 16 * BPITCH;          // 128
    float* sSq  = sSum + 128;                    // 128

    int t = threadIdx.x;
    int warp = t >> 5, lane = t & 31;
    int wm = warp >> 1, wn = warp & 1;           // warp tile: 32 rows x 64 cols
    int g = lane >> 2, qt = lane & 3;
    int bm = blockIdx.y * 128, bn = blockIdx.x * 128;

    float c1 = 1.0f;
    if (PRO == 1) c1 = 1.0f + __ldg(epsp);

    float acc[2][8][4];
    #pragma unroll
    for (int mf = 0; mf < 2; mf++)
        #pragma unroll
        for (int nf = 0; nf < 8; nf++)
            #pragma unroll
            for (int r = 0; r < 4; r++) acc[mf][nf][r] = 0.0f;

    float4 rA[2], rB[2];

    auto load_tile_regs = [&](int kt) {
        #pragma unroll
        for (int i = 0; i < 2; i++) {
            int idx = t + (i << 8);
            int m = idx >> 2, k4 = (idx & 3) << 2;
            int gm = bm + m;
            float4 v = make_float4(0.f, 0.f, 0.f, 0.f);
            if (gm < M) {
                size_t off = ((size_t)gm * K + kt + k4) >> 2;
                v = __ldg(reinterpret_cast<const float4*>(A) + off);
                if (PRO == 1) {
                    float4 u = __ldg(reinterpret_cast<const float4*>(A2) + off);
                    v.x = c1 * v.x + u.x; v.y = c1 * v.y + u.y;
                    v.z = c1 * v.z + u.z; v.w = c1 * v.w + u.w;
                } else if (PRO == 2) {
                    int kg = kt + k4;
                    float4 sc = __ldg(reinterpret_cast<const float4*>(pscale + kg));
                    float4 sh = __ldg(reinterpret_cast<const float4*>(pshift + kg));
                    float y;
                    y = v.x * sc.x + sh.x; v.x = y / (1.0f + __expf(-y));
                    y = v.y * sc.y + sh.y; v.y = y / (1.0f + __expf(-y));
                    y = v.z * sc.z + sh.z; v.z = y / (1.0f + __expf(-y));
                    y = v.w * sc.w + sh.w; v.w = y / (1.0f + __expf(-y));
                }
            }
            rA[i] = v;
            int bk = idx >> 5, n4 = idx & 31;
            rB[i] = __ldg(reinterpret_cast<const float4*>(B + (size_t)(kt + bk) * NC + bn) + n4);
        }
    };
    auto store_tile = [&](int buf) {
        #pragma unroll
        for (int i = 0; i < 2; i++) {
            int idx = t + (i << 8);
            int m = idx >> 2, k4 = (idx & 3) << 2;
            float* ah = Ah + buf * 128 * APITCH + m * APITCH + k4;
            float* al = Al + buf * 128 * APITCH + m * APITCH + k4;
            split_tf32(rA[i].x, ah[0], al[0]);
            split_tf32(rA[i].y, ah[1], al[1]);
            split_tf32(rA[i].z, ah[2], al[2]);
            split_tf32(rA[i].w, ah[3], al[3]);
            int bk = idx >> 5, n4 = idx & 31;
            float* bh = Bh + buf * 16 * BPITCH + bk * BPITCH + (n4 << 2);
            float* bl = Bl + buf * 16 * BPITCH + bk * BPITCH + (n4 << 2);
            split_tf32(rB[i].x, bh[0], bl[0]);
            split_tf32(rB[i].y, bh[1], bl[1]);
            split_tf32(rB[i].z, bh[2], bl[2]);
            split_tf32(rB[i].w, bh[3], bl[3]);
        }
    };

    int ntiles = K / 16;
    load_tile_regs(0);
    store_tile(0);
    __syncthreads();

    for (int tile = 0; tile < ntiles; tile++) {
        if (tile + 1 < ntiles) load_tile_regs((tile + 1) * 16);
        int buf = tile & 1;
        const float* ah = Ah + buf * 128 * APITCH + (wm * 32) * APITCH;
        const float* al = Al + buf * 128 * APITCH + (wm * 32) * APITCH;
        const float* bh = Bh + buf * 16 * BPITCH + wn * 64;
        const float* bl = Bl + buf * 16 * BPITCH + wn * 64;

        #pragma unroll
        for (int ks = 0; ks < 2; ks++) {
            int k0 = ks * 8 + qt;
            uint32_t afh[2][4], afl[2][4], bf[8][2];
            #pragma unroll
            for (int mf = 0; mf < 2; mf++) {
                int r0 = mf * 16 + g;
                afh[mf][0] = __float_as_uint(ah[r0 * APITCH + k0]);
                afh[mf][1] = __float_as_uint(ah[(r0 + 8) * APITCH + k0]);
                afh[mf][2] = __float_as_uint(ah[r0 * APITCH + k0 + 4]);
                afh[mf][3] = __float_as_uint(ah[(r0 + 8) * APITCH + k0 + 4]);
                afl[mf][0] = __float_as_uint(al[r0 * APITCH + k0]);
                afl[mf][1] = __float_as_uint(al[(r0 + 8) * APITCH + k0]);
                afl[mf][2] = __float_as_uint(al[r0 * APITCH + k0 + 4]);
                afl[mf][3] = __float_as_uint(al[(r0 + 8) * APITCH + k0 + 4]);
            }
            #pragma unroll
            for (int nf = 0; nf < 8; nf++) {
                int n0 = nf * 8 + g;
                bf[nf][0] = __float_as_uint(bh[k0 * BPITCH + n0]);
                bf[nf][1] = __float_as_uint(bh[(k0 + 4) * BPITCH + n0]);
            }
            #pragma unroll
            for (int mf = 0; mf < 2; mf++)
                #pragma unroll
                for (int nf = 0; nf < 8; nf++)
                    mma_tf32(acc[mf][nf], afh[mf], bf[nf]);   // hi*hi
            #pragma unroll
            for (int mf = 0; mf < 2; mf++)
                #pragma unroll
                for (int nf = 0; nf < 8; nf++)
                    mma_tf32(acc[mf][nf], afl[mf], bf[nf]);   // lo*hi
            #pragma unroll
            for (int nf = 0; nf < 8; nf++) {
                int n0 = nf * 8 + g;
                bf[nf][0] = __float_as_uint(bl[k0 * BPITCH + n0]);
                bf[nf][1] = __float_as_uint(bl[(k0 + 4) * BPITCH + n0]);
            }
            #pragma unroll
            for (int mf = 0; mf < 2; mf++)
                #pragma unroll
                for (int nf = 0; nf < 8; nf++)
                    mma_tf32(acc[mf][nf], afh[mf], bf[nf]);   // hi*lo
        }
        if (tile + 1 < ntiles) store_tile((tile + 1) & 1);
        __syncthreads();
    }

    // Epilogue: bias, store, column stats
    if (t < 128) { sSum[t] = 0.0f; sSq[t] = 0.0f; }
    __syncthreads();

    float2 bv[8];
    #pragma unroll
    for (int nf = 0; nf < 8; nf++)
        bv[nf] = __ldg(reinterpret_cast<const float2*>(bias + bn + wn * 64 + nf * 8 + 2 * qt));

    float colsum[8][2], colsq[8][2];
    #pragma unroll
    for (int nf = 0; nf < 8; nf++) {
        colsum[nf][0] = 0.f; colsum[nf][1] = 0.f;
        colsq[nf][0] = 0.f;  colsq[nf][1] = 0.f;
    }

    #pragma unroll
    for (int mf = 0; mf < 2; mf++)
        #pragma unroll
        for (int half = 0; half < 2; half++) {
            int row = bm + wm * 32 + mf * 16 + g + 8 * half;
            if (row < M) {
                #pragma unroll
                for (int nf = 0; nf < 8; nf++) {
                    float v0 = acc[mf][nf][2 * half]     + bv[nf].x;
                    float v1 = acc[mf][nf][2 * half + 1] + bv[nf].y;
                    colsum[nf][0] += v0; colsq[nf][0] += v0 * v0;
                    colsum[nf][1] += v1; colsq[nf][1] += v1 * v1;
                    float2 o; o.x = v0; o.y = v1;
                    *reinterpret_cast<float2*>(C + (size_t)row * NC + bn + wn * 64 + nf * 8 + 2 * qt) = o;
                }
            }
        }
    #pragma unroll
    for (int nf = 0; nf < 8; nf++) {
        int cb = wn * 64 + nf * 8 + 2 * qt;
        atomicAdd(&sSum[cb],     colsum[nf][0]);
        atomicAdd(&sSum[cb + 1], colsum[nf][1]);
        atomicAdd(&sSq[cb],      colsq[nf][0]);
        atomicAdd(&sSq[cb + 1],  colsq[nf][1]);
    }
    __syncthreads();
    if (t < 128) {
        atomicAdd(&stats[bn + t],      sSum[t]);
        atomicAdd(&stats[NC + bn + t], sSq[t]);
    }
}

// ---------------------------------------------------------------------------
__global__ void bnfin_kernel(const float* __restrict__ stats,
                             const float* __restrict__ g, const float* __restrict__ beta,
                             float* __restrict__ bnp, int NC, float invN)
{
    int c = blockIdx.x * blockDim.x + threadIdx.x;
    if (c < NC) {
        float mu   = stats[c] * invN;
        float var  = stats[NC + c] * invN - mu * mu;
        float rstd = rsqrtf(var + BN_EPS);
        float sc   = g[c] * rstd;
        bnp[c]      = sc;
        bnp[NC + c] = beta[c] - mu * sc;
    }
}

__global__ void bnsilu_kernel(const float* __restrict__ in, float* __restrict__ out,
                              const float* __restrict__ bnp, int c4mask, int nc4, size_t n4)
{
    size_t i = (size_t)blockIdx.x * blockDim.x + threadIdx.x;
    size_t stride = (size_t)gridDim.x * blockDim.x;
    for (; i < n4; i += stride) {
        int c4 = (int)(i & (size_t)c4mask);
        float4 v  = reinterpret_cast<const float4*>(in)[i];
        float4 sc = reinterpret_cast<const float4*>(bnp)[c4];
        float4 sh = reinterpret_cast<const float4*>(bnp)[nc4 + c4];
        float y0 = v.x * sc.x + sh.x;
        float y1 = v.y * sc.y + sh.y;
        float y2 = v.z * sc.z + sh.z;
        float y3 = v.w * sc.w + sh.w;
        float4 r;
        r.x = y0 / (1.0f + __expf(-y0));
        r.y = y1 / (1.0f + __expf(-y1));
        r.z = y2 / (1.0f + __expf(-y2));
        r.w = y3 / (1.0f + __expf(-y3));
        reinterpret_cast<float4*>(out)[i] = r;
    }
}

// ---------------------------------------------------------------------------
extern "C" void kernel_launch(void* const* d_in, const int* in_sizes, int n_in,
                              void* d_out, int out_size)
{
    const float* x     = (const float*)d_in[0];
    const float* ea    = (const float*)d_in[1];
    const int*   ei    = (const int*)d_in[2];
    const float* We    = (const float*)d_in[3];
    const float* be    = (const float*)d_in[4];
    const float* W1    = (const float*)d_in[5];
    const float* b1    = (const float*)d_in[6];
    const float* g1    = (const float*)d_in[7];
    const float* beta1 = (const float*)d_in[8];
    const float* W2    = (const float*)d_in[9];
    const float* b2    = (const float*)d_in[10];
    const float* g2    = (const float*)d_in[11];
    const float* beta2 = (const float*)d_in[12];
    const float* epsp  = (const float*)d_in[13];

    int N = in_sizes[0] / HID;
    int E = in_sizes[1] / EDIM;
    const int* src = ei;
    const int* dst = ei + E;

    float *aggr, *h1, *h2, *stats1, *stats2, *bnp1, *bnp2;
    cudaGetSymbolAddress((void**)&aggr,   g_aggr);
    cudaGetSymbolAddress((void**)&h1,     g_h1);
    cudaGetSymbolAddress((void**)&h2,     g_h2);
    cudaGetSymbolAddress((void**)&stats1, g_stats1);
    cudaGetSymbolAddress((void**)&stats2, g_stats2);
    cudaGetSymbolAddress((void**)&bnp1,   g_bnp1);
    cudaGetSymbolAddress((void**)&bnp2,   g_bnp2);

    const int GEMM_SMEM = (2 * 128 * 20 * 2 + 2 * 16 * 136 * 2 + 256) * 4;  // 76800 B

    // 1) zero scratch accumulators
    zero_kernel<<<2048, 256>>>(aggr, N * HID);
    zero_kernel<<<4, 256>>>(stats1, 4 * HID);
    zero_kernel<<<2, 256>>>(stats2, 2 * HID);

    // 2) fused edge message + scatter-add (red.v4)
    size_t shmem = (size_t)(EDIM * HID + 32 * EDIM) * sizeof(float);
    cudaFuncSetAttribute(edge_kernel, cudaFuncAttributeMaxDynamicSharedMemorySize, (int)shmem);
    edge_kernel<<<1184, 512, shmem>>>(x, ea, src, dst, We, be, aggr, E);

    // 3) GEMM1 (tensor, 3xTF32): h1 = ((1+eps)*x + aggr) @ W1 + b1, col stats
    cudaFuncSetAttribute(mma_gemm<1>, cudaFuncAttributeMaxDynamicSharedMemorySize, GEMM_SMEM);
    {
        dim3 grid((2 * HID) / 128, (N + 127) / 128);
        mma_gemm<1><<<grid, 256, GEMM_SMEM>>>(x, aggr, W1, b1, nullptr, nullptr,
                                              h1, stats1, N, HID, 2 * HID, epsp);
    }
    // 4) finalize BN1 params
    bnfin_kernel<<<(2 * HID + 255) / 256, 256>>>(stats1, g1, beta1, bnp1, 2 * HID, 1.0f / N);

    // 5) GEMM2 (tensor, 3xTF32) with fused BN1+SiLU prologue: h2 = silu(bn(h1)) @ W2 + b2
    cudaFuncSetAttribute(mma_gemm<2>, cudaFuncAttributeMaxDynamicSharedMemorySize, GEMM_SMEM);
    {
        dim3 grid(HID / 128, (N + 127) / 128);
        mma_gemm<2><<<grid, 256, GEMM_SMEM>>>(h1, nullptr, W2, b2, bnp1, bnp1 + 2 * HID,
                                              h2, stats2, N, 2 * HID, HID, epsp);
    }
    // 6) finalize BN2; final BN + SiLU into d_out
    bnfin_kernel<<<(HID + 255) / 256, 256>>>(stats2, g2, beta2, bnp2, HID, 1.0f / N);
    bnsilu_kernel<<<2048, 256>>>(h2, (float*)d_out, bnp2, 127, 128, (size_t)N * HID / 4);
}

// round 4
// speedup vs baseline: 1.4077x; 1.2448x over previous
#include <cuda_runtime.h>
#include <cuda_bf16.h>
#include <cstdint>
#include <cstddef>

#define HID 512
#define EDIM 64
#define BN_EPS 1e-5f
#define MAXN 50000
#define MAXE 400000

// ---------------------------------------------------------------------------
// Scratch (device globals; allocation in kernel_launch is forbidden)
__device__ float g_aggr[MAXN * HID];
__device__ float g_h1[MAXN * 2 * HID];
__device__ float g_h2[MAXN * HID];
__device__ float g_stats1[4 * HID];
__device__ float g_stats2[2 * HID];
__device__ float g_bnp1[4 * HID];
__device__ float g_bnp2[2 * HID];
__device__ __nv_bfloat16 g_w1t_hi[2 * HID * HID];   // [1024][512] K-major
__device__ __nv_bfloat16 g_w1t_lo[2 * HID * HID];
__device__ __nv_bfloat16 g_w2t_hi[HID * 2 * HID];   // [512][1024] K-major
__device__ __nv_bfloat16 g_w2t_lo[HID * 2 * HID];

// ---------------------------------------------------------------------------
__global__ void zero_kernel(float* __restrict__ p, int n) {
    int i = blockIdx.x * blockDim.x + threadIdx.x;
    int stride = gridDim.x * blockDim.x;
    for (; i < n; i += stride) p[i] = 0.0f;
}

// ---------------------------------------------------------------------------
// bf16 helpers
__device__ __forceinline__ uint32_t pack_bf16(float lo_elem, float hi_elem,
                                              float& res_lo, float& res_hi) {
    __nv_bfloat16 h0 = __float2bfloat16(lo_elem);
    __nv_bfloat16 h1 = __float2bfloat16(hi_elem);
    res_lo = lo_elem - __bfloat162float(h0);
    res_hi = hi_elem - __bfloat162float(h1);
    return (uint32_t)__bfloat16_as_ushort(h0) | ((uint32_t)__bfloat16_as_ushort(h1) << 16);
}
__device__ __forceinline__ uint32_t pack_bf16_only(float a, float b) {
    return (uint32_t)__bfloat16_as_ushort(__float2bfloat16(a))
         | ((uint32_t)__bfloat16_as_ushort(__float2bfloat16(b)) << 16);
}
__device__ __forceinline__ void mma_bf16(float c[4], const uint32_t a[4], const uint32_t b[2]) {
    asm volatile(
        "mma.sync.aligned.m16n8k16.row.col.f32.bf16.bf16.f32 "
        "{%0,%1,%2,%3}, {%4,%5,%6,%7}, {%8,%9}, {%0,%1,%2,%3};\n"
        : "+f"(c[0]), "+f"(c[1]), "+f"(c[2]), "+f"(c[3])
        : "r"(a[0]), "r"(a[1]), "r"(a[2]), "r"(a[3]), "r"(b[0]), "r"(b[1]));
}

// ---------------------------------------------------------------------------
// Weight transpose + bf16 hi/lo split: W[K][NC] f32 -> hi/lo [NC][K] bf16
__global__ void tsplit_kernel(const float* __restrict__ W,
                              __nv_bfloat16* __restrict__ hi, __nv_bfloat16* __restrict__ lo,
                              int K, int NC)
{
    __shared__ float tile[32][33];
    int k0 = blockIdx.y * 32, n0 = blockIdx.x * 32;
    int tx = threadIdx.x, ty = threadIdx.y;   // 32 x 8
    #pragma unroll
    for (int i = 0; i < 32; i += 8)
        tile[ty + i][tx] = W[(size_t)(k0 + ty + i) * NC + n0 + tx];
    __syncthreads();
    #pragma unroll
    for (int i = 0; i < 32; i += 8) {
        float v = tile[tx][ty + i];
        __nv_bfloat16 h = __float2bfloat16(v);
        __nv_bfloat16 l = __float2bfloat16(v - __bfloat162float(h));
        size_t o = (size_t)(n0 + ty + i) * K + k0 + tx;
        hi[o] = h; lo[o] = l;
    }
}

// ---------------------------------------------------------------------------
// Fused edge kernel, column-split for occupancy:
// aggr[dst] += relu(x[src] + edge_attr @ W_e + b_e)
// blockIdx.y selects column half (256 cols). 512 thr = 8 groups x 4 edges,
// each thread owns 4 consecutive columns. W_e half staged in smem (64KB).
__global__ void __launch_bounds__(512, 2) edge_kernel(
    const float* __restrict__ x, const float* __restrict__ ea,
    const int* __restrict__ src, const int* __restrict__ dst,
    const float* __restrict__ We, const float* __restrict__ be,
    float* __restrict__ aggr, int E)
{
    extern __shared__ float smem[];
    float* sWe = smem;                 // 64 * 256 floats = 64 KB
    float* sEa = smem + EDIM * 256;    // 32 * 64 floats  =  8 KB

    int t = threadIdx.x;
    int half = blockIdx.y;             // 0 or 1
    // stage W_e half: 64 rows x 64 float4
    for (int i = t; i < EDIM * 64; i += 512) {
        int r = i >> 6, c = i & 63;
        reinterpret_cast<float4*>(sWe)[i] =
            reinterpret_cast<const float4*>(We)[r * (HID / 4) + half * 64 + c];
    }
    int g  = t >> 6;      // edge-group 0..7 (4 edges each)
    int lc = t & 63;      // column-quad within half
    float4 bev = reinterpret_cast<const float4*>(be)[half * 64 + lc];

    int numTiles = (E + 31) / 32;
    for (int tile = blockIdx.x; tile < numTiles; tile += gridDim.x) {
        int e0 = tile * 32;
        __syncthreads();
        {
            float4 v = make_float4(0.f, 0.f, 0.f, 0.f);
            long long goff = (long long)e0 * EDIM + t * 4;
            if (goff < (long long)E * EDIM)
                v = reinterpret_cast<const float4*>(ea)[e0 * (EDIM / 4) + t];
            reinterpret_cast<float4*>(sEa)[t] = v;
        }
        __syncthreads();

        float acc[4][4];
        #pragma unroll
        for (int e = 0; e < 4; e++) { acc[e][0]=0.f; acc[e][1]=0.f; acc[e][2]=0.f; acc[e][3]=0.f; }

        const float* myEa = sEa + (g * 4) * EDIM;
        #pragma unroll 8
        for (int k = 0; k < EDIM; k++) {
            float4 w = reinterpret_cast<const float4*>(sWe)[k * 64 + lc];
            #pragma unroll
            for (int e = 0; e < 4; e++) {
                float a = myEa[e * EDIM + k];
                acc[e][0] += a * w.x; acc[e][1] += a * w.y;
                acc[e][2] += a * w.z; acc[e][3] += a * w.w;
            }
        }

        #pragma unroll
        for (int e = 0; e < 4; e++) {
            int eg = e0 + g * 4 + e;
            if (eg < E) {
                int s = __ldg(&src[eg]);
                int d = __ldg(&dst[eg]);
                float4 xv = __ldg(reinterpret_cast<const float4*>(x)
                                  + (size_t)s * (HID / 4) + half * 64 + lc);
                float r0 = fmaxf(acc[e][0] + bev.x + xv.x, 0.f);
                float r1 = fmaxf(acc[e][1] + bev.y + xv.y, 0.f);
                float r2 = fmaxf(acc[e][2] + bev.z + xv.z, 0.f);
                float r3 = fmaxf(acc[e][3] + bev.w + xv.w, 0.f);
                float* ap = aggr + (size_t)d * HID + (half * 64 + lc) * 4;
                asm volatile("red.global.add.v4.f32 [%0], {%1,%2,%3,%4};"
                             :: "l"(ap), "f"(r0), "f"(r1), "f"(r2), "f"(r3) : "memory");
            }
        }
    }
}

// ---------------------------------------------------------------------------
// bf16 (3x split) mma.sync GEMM: C[M,NC] = A_eff[M,K] @ W[K,NC] + bias
// W pre-transposed+split: Bhi/Blo [NC][K] bf16 K-major.
// PRO==1: A_eff = (1+eps)*A + A2   PRO==2: A_eff = silu(A*pscale[k]+pshift[k])
// Epilogue: per-column sum & sumsq into stats[2*NC].
// Block 256 thr (8 warps 4x2), tile 128x128x16, double-buffered smem.
// SMEM tiles stored as uint32 (bf16 k-pairs): [128 rows][12 words] (8 used + 4 pad)
#define PITCH 12
#define AH_OFF 0
#define AL_OFF (128 * PITCH)
#define BH_OFF (2 * 128 * PITCH)
#define BL_OFF (3 * 128 * PITCH)
#define BUF_STRIDE (4 * 128 * PITCH)            // one full buffer (u32 words)
#define STAT_OFF (2 * BUF_STRIDE)               // sSum[128], sSq[128] (floats)
#define GEMM_SMEM_BYTES ((2 * BUF_STRIDE + 256) * 4)   // 50176

template<int PRO>
__global__ void __launch_bounds__(256, 2) mma_gemm(
    const float* __restrict__ A, const float* __restrict__ A2,
    const __nv_bfloat16* __restrict__ Bhi, const __nv_bfloat16* __restrict__ Blo,
    const float* __restrict__ bias,
    const float* __restrict__ pscale, const float* __restrict__ pshift,
    float* __restrict__ C, float* __restrict__ stats,
    int M, int K, int NC, const float* __restrict__ epsp)
{
    extern __shared__ uint32_t sm[];
    float* sSum = reinterpret_cast<float*>(sm + STAT_OFF);
    float* sSq  = sSum + 128;

    int t = threadIdx.x;
    int warp = t >> 5, lane = t & 31;
    int wm = warp >> 1, wn = warp & 1;           // warp tile: 32 rows x 64 cols
    int g = lane >> 2, qt = lane & 3;
    int bm = blockIdx.y * 128, bn = blockIdx.x * 128;

    float c1 = 1.0f;
    if (PRO == 1) c1 = 1.0f + __ldg(epsp);

    float acc[2][8][4];
    #pragma unroll
    for (int mf = 0; mf < 2; mf++)
        #pragma unroll
        for (int nf = 0; nf < 8; nf++)
            #pragma unroll
            for (int r = 0; r < 4; r++) acc[mf][nf][r] = 0.0f;

    // register staging for global loads
    float4 rA[2];
    uint4 rBh[1], rBl[1];
    // B: 128 rows x 16 bf16 = 128 x 2 uint4 per split; 256 thr -> 1 uint4 hi + 1 lo each
    // A: 128 x 16 f32 = 512 float4; 2 per thread

    auto load_tile_regs = [&](int kt) {
        #pragma unroll
        for (int i = 0; i < 2; i++) {
            int idx = t + (i << 8);
            int m = idx >> 2, k4 = (idx & 3) << 2;
            int gm = bm + m;
            float4 v = make_float4(0.f, 0.f, 0.f, 0.f);
            if (gm < M) {
                size_t off = ((size_t)gm * K + kt + k4) >> 2;
                v = __ldg(reinterpret_cast<const float4*>(A) + off);
                if (PRO == 1) {
                    float4 u = __ldg(reinterpret_cast<const float4*>(A2) + off);
                    v.x = c1 * v.x + u.x; v.y = c1 * v.y + u.y;
                    v.z = c1 * v.z + u.z; v.w = c1 * v.w + u.w;
                } else {
                    float4 sc = __ldg(reinterpret_cast<const float4*>(pscale + kt + k4));
                    float4 sh = __ldg(reinterpret_cast<const float4*>(pshift + kt + k4));
                    float y;
                    y = v.x * sc.x + sh.x; v.x = y / (1.0f + __expf(-y));
                    y = v.y * sc.y + sh.y; v.y = y / (1.0f + __expf(-y));
                    y = v.z * sc.z + sh.z; v.z = y / (1.0f + __expf(-y));
                    y = v.w * sc.w + sh.w; v.w = y / (1.0f + __expf(-y));
                }
            }
            rA[i] = v;
        }
        {
            int n = t >> 1, h8 = t & 1;       // row, which 8-k chunk
            const __nv_bfloat16* ph = Bhi + (size_t)(bn + n) * K + kt + h8 * 8;
            const __nv_bfloat16* pl = Blo + (size_t)(bn + n) * K + kt + h8 * 8;
            rBh[0] = *reinterpret_cast<const uint4*>(ph);
            rBl[0] = *reinterpret_cast<const uint4*>(pl);
        }
    };
    auto store_tile = [&](int buf) {
        uint32_t* base = sm + buf * BUF_STRIDE;
        #pragma unroll
        for (int i = 0; i < 2; i++) {
            int idx = t + (i << 8);
            int m = idx >> 2, k4 = (idx & 3) << 2;   // k4 in {0,4,8,12}
            float l0, l1, l2, l3;
            uint32_t hw0 = pack_bf16(rA[i].x, rA[i].y, l0, l1);
            uint32_t hw1 = pack_bf16(rA[i].z, rA[i].w, l2, l3);
            uint32_t lw0 = pack_bf16_only(l0, l1);
            uint32_t lw1 = pack_bf16_only(l2, l3);
            int w = k4 >> 1;                          // word index {0,2,4,6}
            base[AH_OFF + m * PITCH + w]     = hw0;
            base[AH_OFF + m * PITCH + w + 1] = hw1;
            base[AL_OFF + m * PITCH + w]     = lw0;
            base[AL_OFF + m * PITCH + w + 1] = lw1;
        }
        {
            int n = t >> 1, h8 = t & 1;
            int w = h8 * 4;
            uint32_t* bh = base + BH_OFF + n * PITCH + w;
            uint32_t* bl = base + BL_OFF + n * PITCH + w;
            bh[0] = rBh[0].x; bh[1] = rBh[0].y; bh[2] = rBh[0].z; bh[3] = rBh[0].w;
            bl[0] = rBl[0].x; bl[1] = rBl[0].y; bl[2] = rBl[0].z; bl[3] = rBl[0].w;
        }
    };

    int ntiles = K / 16;
    load_tile_regs(0);
    store_tile(0);
    __syncthreads();

    for (int tile = 0; tile < ntiles; tile++) {
        if (tile + 1 < ntiles) load_tile_regs((tile + 1) * 16);
        const uint32_t* base = sm + (tile & 1) * BUF_STRIDE;
        const uint32_t* ah = base + AH_OFF + (wm * 32) * PITCH;
        const uint32_t* al = base + AL_OFF + (wm * 32) * PITCH;
        const uint32_t* bh = base + BH_OFF + (wn * 64) * PITCH;
        const uint32_t* bl = base + BL_OFF + (wn * 64) * PITCH;

        uint32_t afh[2][4], afl[2][4], bf[8][2];
        #pragma unroll
        for (int mf = 0; mf < 2; mf++) {
            int r0 = mf * 16 + g;
            afh[mf][0] = ah[r0 * PITCH + qt];
            afh[mf][1] = ah[(r0 + 8) * PITCH + qt];
            afh[mf][2] = ah[r0 * PITCH + qt + 4];
            afh[mf][3] = ah[(r0 + 8) * PITCH + qt + 4];
            afl[mf][0] = al[r0 * PITCH + qt];
            afl[mf][1] = al[(r0 + 8) * PITCH + qt];
            afl[mf][2] = al[r0 * PITCH + qt + 4];
            afl[mf][3] = al[(r0 + 8) * PITCH + qt + 4];
        }
        #pragma unroll
        for (int nf = 0; nf < 8; nf++) {
            int n0 = nf * 8 + g;
            bf[nf][0] = bh[n0 * PITCH + qt];
            bf[nf][1] = bh[n0 * PITCH + qt + 4];
        }
        #pragma unroll
        for (int mf = 0; mf < 2; mf++)
            #pragma unroll
            for (int nf = 0; nf < 8; nf++)
                mma_bf16(acc[mf][nf], afh[mf], bf[nf]);   // hi*hi
        #pragma unroll
        for (int mf = 0; mf < 2; mf++)
            #pragma unroll
            for (int nf = 0; nf < 8; nf++)
                mma_bf16(acc[mf][nf], afl[mf], bf[nf]);   // lo*hi
        #pragma unroll
        for (int nf = 0; nf < 8; nf++) {
            int n0 = nf * 8 + g;
            bf[nf][0] = bl[n0 * PITCH + qt];
            bf[nf][1] = bl[n0 * PITCH + qt + 4];
        }
        #pragma unroll
        for (int mf = 0; mf < 2; mf++)
            #pragma unroll
            for (int nf = 0; nf < 8; nf++)
                mma_bf16(acc[mf][nf], afh[mf], bf[nf]);   // hi*lo
        if (tile + 1 < ntiles) store_tile((tile + 1) & 1);
        __syncthreads();
    }

    // Epilogue: bias, store, column stats
    if (t < 128) { sSum[t] = 0.0f; sSq[t] = 0.0f; }
    __syncthreads();

    float2 bv[8];
    #pragma unroll
    for (int nf = 0; nf < 8; nf++)
        bv[nf] = __ldg(reinterpret_cast<const float2*>(bias + bn + wn * 64 + nf * 8 + 2 * qt));

    float colsum[8][2], colsq[8][2];
    #pragma unroll
    for (int nf = 0; nf < 8; nf++) {
        colsum[nf][0] = 0.f; colsum[nf][1] = 0.f;
        colsq[nf][0] = 0.f;  colsq[nf][1] = 0.f;
    }

    #pragma unroll
    for (int mf = 0; mf < 2; mf++)
        #pragma unroll
        for (int half = 0; half < 2; half++) {
            int row = bm + wm * 32 + mf * 16 + g + 8 * half;
            if (row < M) {
                #pragma unroll
                for (int nf = 0; nf < 8; nf++) {
                    float v0 = acc[mf][nf][2 * half]     + bv[nf].x;
                    float v1 = acc[mf][nf][2 * half + 1] + bv[nf].y;
                    colsum[nf][0] += v0; colsq[nf][0] += v0 * v0;
                    colsum[nf][1] += v1; colsq[nf][1] += v1 * v1;
                    float2 o; o.x = v0; o.y = v1;
                    *reinterpret_cast<float2*>(C + (size_t)row * NC + bn + wn * 64 + nf * 8 + 2 * qt) = o;
                }
            }
        }
    #pragma unroll
    for (int nf = 0; nf < 8; nf++) {
        int cb = wn * 64 + nf * 8 + 2 * qt;
        atomicAdd(&sSum[cb],     colsum[nf][0]);
        atomicAdd(&sSum[cb + 1], colsum[nf][1]);
        atomicAdd(&sSq[cb],      colsq[nf][0]);
        atomicAdd(&sSq[cb + 1],  colsq[nf][1]);
    }
    __syncthreads();
    if (t < 128) {
        atomicAdd(&stats[bn + t],      sSum[t]);
        atomicAdd(&stats[NC + bn + t], sSq[t]);
    }
}

// ---------------------------------------------------------------------------
__global__ void bnfin_kernel(const float* __restrict__ stats,
                             const float* __restrict__ g, const float* __restrict__ beta,
                             float* __restrict__ bnp, int NC, float invN)
{
    int c = blockIdx.x * blockDim.x + threadIdx.x;
    if (c < NC) {
        float mu   = stats[c] * invN;
        float var  = stats[NC + c] * invN - mu * mu;
        float rstd = rsqrtf(var + BN_EPS);
        float sc   = g[c] * rstd;
        bnp[c]      = sc;
        bnp[NC + c] = beta[c] - mu * sc;
    }
}

__global__ void bnsilu_kernel(const float* __restrict__ in, float* __restrict__ out,
                              const float* __restrict__ bnp, int c4mask, int nc4, size_t n4)
{
    size_t i = (size_t)blockIdx.x * blockDim.x + threadIdx.x;
    size_t stride = (size_t)gridDim.x * blockDim.x;
    for (; i < n4; i += stride) {
        int c4 = (int)(i & (size_t)c4mask);
        float4 v  = reinterpret_cast<const float4*>(in)[i];
        float4 sc = reinterpret_cast<const float4*>(bnp)[c4];
        float4 sh = reinterpret_cast<const float4*>(bnp)[nc4 + c4];
        float y0 = v.x * sc.x + sh.x;
        float y1 = v.y * sc.y + sh.y;
        float y2 = v.z * sc.z + sh.z;
        float y3 = v.w * sc.w + sh.w;
        float4 r;
        r.x = y0 / (1.0f + __expf(-y0));
        r.y = y1 / (1.0f + __expf(-y1));
        r.z = y2 / (1.0f + __expf(-y2));
        r.w = y3 / (1.0f + __expf(-y3));
        reinterpret_cast<float4*>(out)[i] = r;
    }
}

// ---------------------------------------------------------------------------
extern "C" void kernel_launch(void* const* d_in, const int* in_sizes, int n_in,
                              void* d_out, int out_size)
{
    const float* x     = (const float*)d_in[0];
    const float* ea    = (const float*)d_in[1];
    const int*   ei    = (const int*)d_in[2];
    const float* We    = (const float*)d_in[3];
    const float* be    = (const float*)d_in[4];
    const float* W1    = (const float*)d_in[5];
    const float* b1    = (const float*)d_in[6];
    const float* g1    = (const float*)d_in[7];
    const float* beta1 = (const float*)d_in[8];
    const float* W2    = (const float*)d_in[9];
    const float* b2    = (const float*)d_in[10];
    const float* g2    = (const float*)d_in[11];
    const float* beta2 = (const float*)d_in[12];
    const float* epsp  = (const float*)d_in[13];

    int N = in_sizes[0] / HID;
    int E = in_sizes[1] / EDIM;
    const int* src = ei;
    const int* dst = ei + E;

    float *aggr, *h1, *h2, *stats1, *stats2, *bnp1, *bnp2;
    __nv_bfloat16 *w1h, *w1l, *w2h, *w2l;
    cudaGetSymbolAddress((void**)&aggr,   g_aggr);
    cudaGetSymbolAddress((void**)&h1,     g_h1);
    cudaGetSymbolAddress((void**)&h2,     g_h2);
    cudaGetSymbolAddress((void**)&stats1, g_stats1);
    cudaGetSymbolAddress((void**)&stats2, g_stats2);
    cudaGetSymbolAddress((void**)&bnp1,   g_bnp1);
    cudaGetSymbolAddress((void**)&bnp2,   g_bnp2);
    cudaGetSymbolAddress((void**)&w1h,    g_w1t_hi);
    cudaGetSymbolAddress((void**)&w1l,    g_w1t_lo);
    cudaGetSymbolAddress((void**)&w2h,    g_w2t_hi);
    cudaGetSymbolAddress((void**)&w2l,    g_w2t_lo);

    // 1) zero accumulators
    zero_kernel<<<2048, 256>>>(aggr, N * HID);
    zero_kernel<<<4, 256>>>(stats1, 4 * HID);
    zero_kernel<<<2, 256>>>(stats2, 2 * HID);

    // 2) weight transpose + bf16 split (K-major [N][K])
    tsplit_kernel<<<dim3(2 * HID / 32, HID / 32), dim3(32, 8)>>>(W1, w1h, w1l, HID, 2 * HID);
    tsplit_kernel<<<dim3(HID / 32, 2 * HID / 32), dim3(32, 8)>>>(W2, w2h, w2l, 2 * HID, HID);

    // 3) fused edge message + scatter-add (column-split, 2 CTAs/SM)
    size_t shmem = (size_t)(EDIM * 256 + 32 * EDIM) * sizeof(float);  // 72 KB
    cudaFuncSetAttribute(edge_kernel, cudaFuncAttributeMaxDynamicSharedMemorySize, (int)shmem);
    edge_kernel<<<dim3(592, 2), 512, shmem>>>(x, ea, src, dst, We, be, aggr, E);

    // 4) GEMM1 (bf16-split mma): h1 = ((1+eps)*x + aggr) @ W1 + b1, col stats
    cudaFuncSetAttribute(mma_gemm<1>, cudaFuncAttributeMaxDynamicSharedMemorySize, GEMM_SMEM_BYTES);
    cudaFuncSetAttribute(mma_gemm<2>, cudaFuncAttributeMaxDynamicSharedMemorySize, GEMM_SMEM_BYTES);
    {
        dim3 grid((2 * HID) / 128, (N + 127) / 128);
        mma_gemm<1><<<grid, 256, GEMM_SMEM_BYTES>>>(x, aggr, w1h, w1l, b1, nullptr, nullptr,
                                                    h1, stats1, N, HID, 2 * HID, epsp);
    }
    // 5) finalize BN1 params
    bnfin_kernel<<<(2 * HID + 255) / 256, 256>>>(stats1, g1, beta1, bnp1, 2 * HID, 1.0f / N);

    // 6) GEMM2 with fused BN1+SiLU prologue: h2 = silu(bn(h1)) @ W2 + b2, col stats
    {
        dim3 grid(HID / 128, (N + 127) / 128);
        mma_gemm<2><<<grid, 256, GEMM_SMEM_BYTES>>>(h1, nullptr, w2h, w2l, b2, bnp1, bnp1 + 2 * HID,
                                                    h2, stats2, N, 2 * HID, HID, epsp);
    }
    // 7) finalize BN2; final BN + SiLU into d_out
    bnfin_kernel<<<(HID + 255) / 256, 256>>>(stats2, g2, beta2, bnp2, HID, 1.0f / N);
    bnsilu_kernel<<<2048, 256>>>(h2, (float*)d_out, bnp2, 127, 128, (size_t)N * HID / 4);
}

// round 6
// speedup vs baseline: 1.5471x; 1.0990x over previous
#include <cuda_runtime.h>
#include <cuda_bf16.h>
#include <cstdint>
#include <cstddef>

#define HID 512
#define EDIM 64
#define BN_EPS 1e-5f
#define MAXN 50000
#define MAXE 400000

// ---------------------------------------------------------------------------
// Scratch (device globals; allocation in kernel_launch is forbidden)
__device__ float g_aggr[MAXN * HID];
__device__ float g_h1[MAXN * 2 * HID];
__device__ float g_h2[MAXN * HID];
__device__ float g_stats1[4 * HID];
__device__ float g_stats2[2 * HID];
__device__ float g_bnp1[4 * HID];
__device__ float g_bnp2[2 * HID];
__device__ __nv_bfloat16 g_w1t_hi[2 * HID * HID];   // [1024][512] K-major
__device__ __nv_bfloat16 g_w1t_lo[2 * HID * HID];
__device__ __nv_bfloat16 g_w2t_hi[HID * 2 * HID];   // [512][1024] K-major
__device__ __nv_bfloat16 g_w2t_lo[HID * 2 * HID];
__device__ __nv_bfloat16 g_wet_hi[HID * EDIM];      // [512][64] K-major
__device__ __nv_bfloat16 g_wet_lo[HID * EDIM];

// ---------------------------------------------------------------------------
__global__ void zero_kernel(float* __restrict__ p, int n) {
    int i = blockIdx.x * blockDim.x + threadIdx.x;
    int stride = gridDim.x * blockDim.x;
    for (; i < n; i += stride) p[i] = 0.0f;
}

// ---------------------------------------------------------------------------
__device__ __forceinline__ uint32_t smem_u32(const void* p) {
    uint32_t a;
    asm("{ .reg .u64 t; cvta.to.shared.u64 t, %1; cvt.u32.u64 %0, t; }" : "=r"(a) : "l"(p));
    return a;
}
__device__ __forceinline__ void split2(float a, float b, uint32_t& hw, uint32_t& lw) {
    __nv_bfloat16 ha = __float2bfloat16(a), hb = __float2bfloat16(b);
    float ra = a - __bfloat162float(ha), rb = b - __bfloat162float(hb);
    hw = (uint32_t)__bfloat16_as_ushort(ha) | ((uint32_t)__bfloat16_as_ushort(hb) << 16);
    lw = (uint32_t)__bfloat16_as_ushort(__float2bfloat16(ra))
       | ((uint32_t)__bfloat16_as_ushort(__float2bfloat16(rb)) << 16);
}
__device__ __forceinline__ void mma_bf16(float c[4], const uint32_t a[4], const uint32_t b[2]) {
    asm volatile(
        "mma.sync.aligned.m16n8k16.row.col.f32.bf16.bf16.f32 "
        "{%0,%1,%2,%3}, {%4,%5,%6,%7}, {%8,%9}, {%0,%1,%2,%3};\n"
        : "+f"(c[0]), "+f"(c[1]), "+f"(c[2]), "+f"(c[3])
        : "r"(a[0]), "r"(a[1]), "r"(a[2]), "r"(a[3]), "r"(b[0]), "r"(b[1]));
}
__device__ __forceinline__ void ldm_x4(uint32_t r[4], uint32_t addr) {
    asm volatile("ldmatrix.sync.aligned.m8n8.x4.shared.b16 {%0,%1,%2,%3}, [%4];"
        : "=r"(r[0]), "=r"(r[1]), "=r"(r[2]), "=r"(r[3]) : "r"(addr));
}
__device__ __forceinline__ void cpasync16(uint32_t daddr, const void* g) {
    asm volatile("cp.async.cg.shared.global [%0], [%1], 16;" :: "r"(daddr), "l"(g) : "memory");
}
#define CP_COMMIT() asm volatile("cp.async.commit_group;" ::: "memory")
#define CP_WAIT0()  asm volatile("cp.async.wait_group 0;" ::: "memory")

// ---------------------------------------------------------------------------
// Weight transpose + bf16 hi/lo split: W[K][NC] f32 -> hi/lo [NC][K] bf16
__global__ void tsplit_kernel(const float* __restrict__ W,
                              __nv_bfloat16* __restrict__ hi, __nv_bfloat16* __restrict__ lo,
                              int K, int NC)
{
    __shared__ float tile[32][33];
    int k0 = blockIdx.y * 32, n0 = blockIdx.x * 32;
    int tx = threadIdx.x, ty = threadIdx.y;   // 32 x 8
    #pragma unroll
    for (int i = 0; i < 32; i += 8)
        tile[ty + i][tx] = W[(size_t)(k0 + ty + i) * NC + n0 + tx];
    __syncthreads();
    #pragma unroll
    for (int i = 0; i < 32; i += 8) {
        float v = tile[tx][ty + i];
        __nv_bfloat16 h = __float2bfloat16(v);
        __nv_bfloat16 l = __float2bfloat16(v - __bfloat162float(h));
        size_t o = (size_t)(n0 + ty + i) * K + k0 + tx;
        hi[o] = h; lo[o] = l;
    }
}

// ---------------------------------------------------------------------------
// Tensorized edge kernel: aggr[dst] += relu(x[src] + ea @ We + be)
// CTA = 128 edges; 4 column passes of 128. bf16-split 3x MMA.
// smem (u32 words): EA hi/lo 128x36 each, B hi/lo 128x36 each, idx 256, stage 8*16*68
#define EP 36
#define EAH 0
#define EAL 4608
#define EBH 9216
#define EBL 13824
#define EIDX 18432
#define ESTG 18688
#define EDGE_SMEM_BYTES ((18688 + 8 * 16 * 68) * 4)   // 109568

__global__ void __launch_bounds__(256, 2) edge_mma(
    const float* __restrict__ x, const float* __restrict__ ea,
    const int* __restrict__ src, const int* __restrict__ dst,
    const __nv_bfloat16* __restrict__ weth, const __nv_bfloat16* __restrict__ wetl,
    const float* __restrict__ be, float* __restrict__ aggr, int E)
{
    extern __shared__ uint32_t sm[];
    uint32_t sb = smem_u32(sm);
    int t = threadIdx.x, warp = t >> 5, lane = t & 31;
    int wm = warp >> 1, wn = warp & 1;
    int g = lane >> 2, qt = lane & 3;
    int lr = lane & 7, lm1 = (lane >> 3) & 1, lm2 = lane >> 4;
    int e0 = blockIdx.x * 128;

    // indices to smem
    if (t < 128) {
        int e = e0 + t;
        ((int*)sm)[EIDX + t] = (e < E) ? __ldg(&src[e]) : 0;
    } else {
        int e = e0 + (t - 128);
        ((int*)sm)[EIDX + t] = (e < E) ? __ldg(&dst[e]) : 0;
    }

    // ea tile load + split: 128 rows x 64 f32
    #pragma unroll
    for (int i = 0; i < 8; i++) {
        int idx = t + (i << 8);
        int row = idx >> 4, f4 = idx & 15;
        int e = e0 + row;
        float4 v = make_float4(0.f, 0.f, 0.f, 0.f);
        if (e < E) v = __ldg(reinterpret_cast<const float4*>(ea + (size_t)e * EDIM + f4 * 4));
        uint32_t h0, l0, h1, l1;
        split2(v.x, v.y, h0, l0);
        split2(v.z, v.w, h1, l1);
        int w = EAH + row * EP + f4 * 2;
        sm[w] = h0; sm[w + 1] = h1;
        sm[w + EAL] = l0; sm[w + EAL + 1] = l1;
    }

    int arow = wm * 32 + lr + 8 * lm1;
    int brow = wn * 64 + lr + 8 * lm2;
    float* stg = reinterpret_cast<float*>(sm + ESTG) + warp * (16 * 68);

    #pragma unroll 1
    for (int pass = 0; pass < 4; pass++) {
        __syncthreads();   // prior pass done (or ea/idx stores visible)
        // B tile for this pass via cp.async: 2 splits x 128 n x 64 k bf16
        // = 2048 16B chunks = 8 iters x 256 threads
        #pragma unroll
        for (int i = 0; i < 8; i++) {
            int cell = t + (i << 8);
            int split = cell >> 10, rem = cell & 1023;
            int n = rem >> 3, ch = rem & 7;
            const __nv_bfloat16* gp = (split ? wetl : weth) + (size_t)(pass * 128 + n) * EDIM + ch * 8;
            cpasync16(sb + ((split ? EBL : EBH) + n * EP + ch * 4) * 4, gp);
        }
        CP_COMMIT();
        CP_WAIT0();
        __syncthreads();

        float acc[2][8][4];
        #pragma unroll
        for (int mf = 0; mf < 2; mf++)
            #pragma unroll
            for (int nf = 0; nf < 8; nf++)
                #pragma unroll
                for (int r = 0; r < 4; r++) acc[mf][nf][r] = 0.0f;

        #pragma unroll
        for (int ks = 0; ks < 4; ks++) {
            uint32_t af[2][4], al2[2][4], bb[8][2];
            #pragma unroll
            for (int mf = 0; mf < 2; mf++) {
                ldm_x4(af[mf],  sb + (EAH + (arow + mf * 16) * EP + ks * 8 + 4 * lm2) * 4);
                ldm_x4(al2[mf], sb + (EAL + (arow + mf * 16) * EP + ks * 8 + 4 * lm2) * 4);
            }
            #pragma unroll
            for (int np = 0; np < 4; np++) {
                uint32_t r[4];
                ldm_x4(r, sb + (EBH + (brow + np * 16) * EP + ks * 8 + 4 * lm1) * 4);
                bb[np * 2][0] = r[0]; bb[np * 2][1] = r[1];
                bb[np * 2 + 1][0] = r[2]; bb[np * 2 + 1][1] = r[3];
            }
            #pragma unroll
            for (int mf = 0; mf < 2; mf++)
                #pragma unroll
                for (int nf = 0; nf < 8; nf++)
                    mma_bf16(acc[mf][nf], af[mf], bb[nf]);    // hi*hi
            #pragma unroll
            for (int mf = 0; mf < 2; mf++)
                #pragma unroll
                for (int nf = 0; nf < 8; nf++)
                    mma_bf16(acc[mf][nf], al2[mf], bb[nf]);   // lo*hi
            #pragma unroll
            for (int np = 0; np < 4; np++) {
                uint32_t r[4];
                ldm_x4(r, sb + (EBL + (brow + np * 16) * EP + ks * 8 + 4 * lm1) * 4);
                bb[np * 2][0] = r[0]; bb[np * 2][1] = r[1];
                bb[np * 2 + 1][0] = r[2]; bb[np * 2 + 1][1] = r[3];
            }
            #pragma unroll
            for (int mf = 0; mf < 2; mf++)
                #pragma unroll
                for (int nf = 0; nf < 8; nf++)
                    mma_bf16(acc[mf][nf], af[mf], bb[nf]);    // hi*lo
        }

        // epilogue: stage -> gather x -> relu -> RED.v4
        #pragma unroll
        for (int mf = 0; mf < 2; mf++) {
            __syncwarp();
            #pragma unroll
            for (int nf = 0; nf < 8; nf++)
                #pragma unroll
                for (int h = 0; h < 2; h++) {
                    float2 o;
                    o.x = acc[mf][nf][2 * h];
                    o.y = acc[mf][nf][2 * h + 1];
                    *reinterpret_cast<float2*>(&stg[(g + 8 * h) * 68 + nf * 8 + 2 * qt]) = o;
                }
            __syncwarp();
            int r16 = lane & 15, half = lane >> 4;
            int loc = wm * 32 + mf * 16 + r16;
            int e = e0 + loc;
            if (e < E) {
                int s = ((int*)sm)[EIDX + loc];
                int d = ((int*)sm)[EIDX + 128 + loc];
                int cg = pass * 128 + wn * 64 + half * 32;
                const float* xr = x + (size_t)s * HID + cg;
                float* ar = aggr + (size_t)d * HID + cg;
                const float* br = be + cg;
                const float* sr = stg + r16 * 68 + half * 32;
                #pragma unroll
                for (int c = 0; c < 8; c++) {
                    float4 m4 = *reinterpret_cast<const float4*>(sr + c * 4);
                    float4 xv = __ldg(reinterpret_cast<const float4*>(xr + c * 4));
                    float4 bv = __ldg(reinterpret_cast<const float4*>(br + c * 4));
                    float r0 = fmaxf(m4.x + xv.x + bv.x, 0.f);
                    float r1 = fmaxf(m4.y + xv.y + bv.y, 0.f);
                    float r2 = fmaxf(m4.z + xv.z + bv.z, 0.f);
                    float r3 = fmaxf(m4.w + xv.w + bv.w, 0.f);
                    asm volatile("red.global.add.v4.f32 [%0], {%1,%2,%3,%4};"
                                 :: "l"(ar + c * 4), "f"(r0), "f"(r1), "f"(r2), "f"(r3) : "memory");
                }
            }
        }
    }
}

// ---------------------------------------------------------------------------
// bf16-split (3x) HMMA GEMM, BK=32, ldmatrix frags, cp.async B.
// C[M,NC] = A_eff[M,K] @ W[K,NC] + bias; per-column sum/sumsq into stats.
// PRO==1: A_eff = (1+eps)*A + A2   PRO==2: A_eff = silu(A*pscale[k]+pshift[k])
#define GP 20
#define GAH 0
#define GAL 2560
#define GBH 5120
#define GBL 7680
#define GBUF 10240
#define GSTAT 20480
#define GEMM_SMEM_BYTES ((2 * GBUF + 256) * 4)   // 82944

template<int PRO>
__global__ void __launch_bounds__(256, 2) mma_gemm(
    const float* __restrict__ A, const float* __restrict__ A2,
    const __nv_bfloat16* __restrict__ Bhi, const __nv_bfloat16* __restrict__ Blo,
    const float* __restrict__ bias,
    const float* __restrict__ pscale, const float* __restrict__ pshift,
    float* __restrict__ C, float* __restrict__ stats,
    int M, int K, int NC, const float* __restrict__ epsp)
{
    extern __shared__ uint32_t sm[];
    uint32_t sb = smem_u32(sm);
    float* sSum = reinterpret_cast<float*>(sm + GSTAT);
    float* sSq  = sSum + 128;

    int t = threadIdx.x, warp = t >> 5, lane = t & 31;
    int wm = warp >> 1, wn = warp & 1;
    int g = lane >> 2, qt = lane & 3;
    int lr = lane & 7, lm1 = (lane >> 3) & 1, lm2 = lane >> 4;
    int bm = blockIdx.y * 128, bn = blockIdx.x * 128;
    int arow = wm * 32 + lr + 8 * lm1;
    int brow = wn * 64 + lr + 8 * lm2;

    float c1 = 1.0f;
    if (PRO == 1) c1 = 1.0f + __ldg(epsp);

    float acc[2][8][4];
    #pragma unroll
    for (int mf = 0; mf < 2; mf++)
        #pragma unroll
        for (int nf = 0; nf < 8; nf++)
            #pragma unroll
            for (int r = 0; r < 4; r++) acc[mf][nf][r] = 0.0f;

    float4 rA[4];
    auto loadA = [&](int kt) {
        #pragma unroll
        for (int i = 0; i < 4; i++) {
            int idx = t + (i << 8);
            int m = idx >> 3, k4 = (idx & 7) << 2;
            int gm = bm + m;
            float4 v = make_float4(0.f, 0.f, 0.f, 0.f);
            if (gm < M) {
                size_t off = ((size_t)gm * K + kt + k4) >> 2;
                v = __ldg(reinterpret_cast<const float4*>(A) + off);
                if (PRO == 1) {
                    float4 u = __ldg(reinterpret_cast<const float4*>(A2) + off);
                    v.x = c1 * v.x + u.x; v.y = c1 * v.y + u.y;
                    v.z = c1 * v.z + u.z; v.w = c1 * v.w + u.w;
                } else {
                    float4 sc = __ldg(reinterpret_cast<const float4*>(pscale + kt + k4));
                    float4 sh = __ldg(reinterpret_cast<const float4*>(pshift + kt + k4));
                    float y;
                    y = v.x * sc.x + sh.x; v.x = y / (1.0f + __expf(-y));
                    y = v.y * sc.y + sh.y; v.y = y / (1.0f + __expf(-y));
                    y = v.z * sc.z + sh.z; v.z = y / (1.0f + __expf(-y));
                    y = v.w * sc.w + sh.w; v.w = y / (1.0f + __expf(-y));
                }
            }
            rA[i] = v;
        }
    };
    auto storeA = [&](int buf) {
        uint32_t b0 = buf ? GBUF : 0;
        #pragma unroll
        for (int i = 0; i < 4; i++) {
            int idx = t + (i << 8);
            int m = idx >> 3, k4 = (idx & 7) << 2;
            uint32_t h0, l0, h1, l1;
            split2(rA[i].x, rA[i].y, h0, l0);
            split2(rA[i].z, rA[i].w, h1, l1);
            int w = b0 + m * GP + (k4 >> 1);
            sm[GAH + w] = h0; sm[GAH + w + 1] = h1;
            sm[GAL + w] = l0; sm[GAL + w + 1] = l1;
        }
    };
    auto issueB = [&](int kt, int buf) {
        uint32_t b0 = buf ? GBUF : 0;
        // 2 splits x 128 n x 4 chunks(16B) = 1024 cells = 4 iters x 256 thr
        #pragma unroll
        for (int i = 0; i < 4; i++) {
            int cell = t + (i << 8);
            int split = cell >> 9, rem = cell & 511;
            int n = rem >> 2, ch = rem & 3;
            const __nv_bfloat16* gp = (split ? Blo : Bhi) + (size_t)(bn + n) * K + kt + ch * 8;
            cpasync16(sb + (b0 + (split ? GBL : GBH) + n * GP + ch * 4) * 4, gp);
        }
    };

    int S = K / 32;
    issueB(0, 0); CP_COMMIT();
    loadA(0);
    storeA(0);
    CP_WAIT0();
    __syncthreads();

    for (int s = 0; s < S; s++) {
        if (s + 1 < S) { issueB((s + 1) * 32, (s + 1) & 1); CP_COMMIT(); loadA((s + 1) * 32); }
        uint32_t b0 = (s & 1) ? GBUF : 0;
        #pragma unroll
        for (int ks = 0; ks < 2; ks++) {
            uint32_t af[2][4], al2[2][4], bb[8][2];
            #pragma unroll
            for (int mf = 0; mf < 2; mf++) {
                ldm_x4(af[mf],  sb + (b0 + GAH + (arow + mf * 16) * GP + ks * 8 + 4 * lm2) * 4);
                ldm_x4(al2[mf], sb + (b0 + GAL + (arow + mf * 16) * GP + ks * 8 + 4 * lm2) * 4);
            }
            #pragma unroll
            for (int np = 0; np < 4; np++) {
                uint32_t r[4];
                ldm_x4(r, sb + (b0 + GBH + (brow + np * 16) * GP + ks * 8 + 4 * lm1) * 4);
                bb[np * 2][0] = r[0]; bb[np * 2][1] = r[1];
                bb[np * 2 + 1][0] = r[2]; bb[np * 2 + 1][1] = r[3];
            }
            #pragma unroll
            for (int mf = 0; mf < 2; mf++)
                #pragma unroll
                for (int nf = 0; nf < 8; nf++)
                    mma_bf16(acc[mf][nf], af[mf], bb[nf]);    // hi*hi
            #pragma unroll
            for (int mf = 0; mf < 2; mf++)
                #pragma unroll
                for (int nf = 0; nf < 8; nf++)
                    mma_bf16(acc[mf][nf], al2[mf], bb[nf]);   // lo*hi
            #pragma unroll
            for (int np = 0; np < 4; np++) {
                uint32_t r[4];
                ldm_x4(r, sb + (b0 + GBL + (brow + np * 16) * GP + ks * 8 + 4 * lm1) * 4);
                bb[np * 2][0] = r[0]; bb[np * 2][1] = r[1];
                bb[np * 2 + 1][0] = r[2]; bb[np * 2 + 1][1] = r[3];
            }
            #pragma unroll
            for (int mf = 0; mf < 2; mf++)
                #pragma unroll
                for (int nf = 0; nf < 8; nf++)
                    mma_bf16(acc[mf][nf], af[mf], bb[nf]);    // hi*lo
        }
        if (s + 1 < S) storeA((s + 1) & 1);
        CP_WAIT0();
        __syncthreads();
    }

    // Epilogue: bias, store, column stats
    if (t < 128) { sSum[t] = 0.0f; sSq[t] = 0.0f; }
    __syncthreads();

    float2 bv[8];
    #pragma unroll
    for (int nf = 0; nf < 8; nf++)
        bv[nf] = __ldg(reinterpret_cast<const float2*>(bias + bn + wn * 64 + nf * 8 + 2 * qt));

    float colsum[8][2], colsq[8][2];
    #pragma unroll
    for (int nf = 0; nf < 8; nf++) {
        colsum[nf][0] = 0.f; colsum[nf][1] = 0.f;
        colsq[nf][0] = 0.f;  colsq[nf][1] = 0.f;
    }

    #pragma unroll
    for (int mf = 0; mf < 2; mf++)
        #pragma unroll
        for (int half = 0; half < 2; half++) {
            int row = bm + wm * 32 + mf * 16 + g + 8 * half;
            if (row < M) {
                #pragma unroll
                for (int nf = 0; nf < 8; nf++) {
                    float v0 = acc[mf][nf][2 * half]     + bv[nf].x;
                    float v1 = acc[mf][nf][2 * half + 1] + bv[nf].y;
                    colsum[nf][0] += v0; colsq[nf][0] += v0 * v0;
                    colsum[nf][1] += v1; colsq[nf][1] += v1 * v1;
                    float2 o; o.x = v0; o.y = v1;
                    *reinterpret_cast<float2*>(C + (size_t)row * NC + bn + wn * 64 + nf * 8 + 2 * qt) = o;
                }
            }
        }
    #pragma unroll
    for (int nf = 0; nf < 8; nf++) {
        int cb = wn * 64 + nf * 8 + 2 * qt;
        atomicAdd(&sSum[cb],     colsum[nf][0]);
        atomicAdd(&sSum[cb + 1], colsum[nf][1]);
        atomicAdd(&sSq[cb],      colsq[nf][0]);
        atomicAdd(&sSq[cb + 1],  colsq[nf][1]);
    }
    __syncthreads();
    if (t < 128) {
        atomicAdd(&stats[bn + t],      sSum[t]);
        atomicAdd(&stats[NC + bn + t], sSq[t]);
    }
}

// ---------------------------------------------------------------------------
__global__ void bnfin_kernel(const float* __restrict__ stats,
                             const float* __restrict__ g, const float* __restrict__ beta,
                             float* __restrict__ bnp, int NC, float invN)
{
    int c = blockIdx.x * blockDim.x + threadIdx.x;
    if (c < NC) {
        float mu   = stats[c] * invN;
        float var  = stats[NC + c] * invN - mu * mu;
        float rstd = rsqrtf(var + BN_EPS);
        float sc   = g[c] * rstd;
        bnp[c]      = sc;
        bnp[NC + c] = beta[c] - mu * sc;
    }
}

__global__ void bnsilu_kernel(const float* __restrict__ in, float* __restrict__ out,
                              const float* __restrict__ bnp, int c4mask, int nc4, size_t n4)
{
    size_t i = (size_t)blockIdx.x * blockDim.x + threadIdx.x;
    size_t stride = (size_t)gridDim.x * blockDim.x;
    for (; i < n4; i += stride) {
        int c4 = (int)(i & (size_t)c4mask);
        float4 v  = reinterpret_cast<const float4*>(in)[i];
        float4 sc = reinterpret_cast<const float4*>(bnp)[c4];
        float4 sh = reinterpret_cast<const float4*>(bnp)[nc4 + c4];
        float y0 = v.x * sc.x + sh.x;
        float y1 = v.y * sc.y + sh.y;
        float y2 = v.z * sc.z + sh.z;
        float y3 = v.w * sc.w + sh.w;
        float4 r;
        r.x = y0 / (1.0f + __expf(-y0));
        r.y = y1 / (1.0f + __expf(-y1));
        r.z = y2 / (1.0f + __expf(-y2));
        r.w = y3 / (1.0f + __expf(-y3));
        reinterpret_cast<float4*>(out)[i] = r;
    }
}

// ---------------------------------------------------------------------------
extern "C" void kernel_launch(void* const* d_in, const int* in_sizes, int n_in,
                              void* d_out, int out_size)
{
    const float* x     = (const float*)d_in[0];
    const float* ea    = (const float*)d_in[1];
    const int*   ei    = (const int*)d_in[2];
    const float* We    = (const float*)d_in[3];
    const float* be    = (const float*)d_in[4];
    const float* W1    = (const float*)d_in[5];
    const float* b1    = (const float*)d_in[6];
    const float* g1    = (const float*)d_in[7];
    const float* beta1 = (const float*)d_in[8];
    const float* W2    = (const float*)d_in[9];
    const float* b2    = (const float*)d_in[10];
    const float* g2    = (const float*)d_in[11];
    const float* beta2 = (const float*)d_in[12];
    const float* epsp  = (const float*)d_in[13];

    int N = in_sizes[0] / HID;
    int E = in_sizes[1] / EDIM;
    const int* src = ei;
    const int* dst = ei + E;

    float *aggr, *h1, *h2, *stats1, *stats2, *bnp1, *bnp2;
    __nv_bfloat16 *w1h, *w1l, *w2h, *w2l, *weh, *wel;
    cudaGetSymbolAddress((void**)&aggr,   g_aggr);
    cudaGetSymbolAddress((void**)&h1,     g_h1);
    cudaGetSymbolAddress((void**)&h2,     g_h2);
    cudaGetSymbolAddress((void**)&stats1, g_stats1);
    cudaGetSymbolAddress((void**)&stats2, g_stats2);
    cudaGetSymbolAddress((void**)&bnp1,   g_bnp1);
    cudaGetSymbolAddress((void**)&bnp2,   g_bnp2);
    cudaGetSymbolAddress((void**)&w1h,    g_w1t_hi);
    cudaGetSymbolAddress((void**)&w1l,    g_w1t_lo);
    cudaGetSymbolAddress((void**)&w2h,    g_w2t_hi);
    cudaGetSymbolAddress((void**)&w2l,    g_w2t_lo);
    cudaGetSymbolAddress((void**)&weh,    g_wet_hi);
    cudaGetSymbolAddress((void**)&wel,    g_wet_lo);

    // 1) zero accumulators
    zero_kernel<<<2048, 256>>>(aggr, N * HID);
    zero_kernel<<<4, 256>>>(stats1, 4 * HID);
    zero_kernel<<<2, 256>>>(stats2, 2 * HID);

    // 2) weight transpose + bf16 split (K-major [N][K])
    tsplit_kernel<<<dim3(HID / 32, EDIM / 32), dim3(32, 8)>>>(We, weh, wel, EDIM, HID);
    tsplit_kernel<<<dim3(2 * HID / 32, HID / 32), dim3(32, 8)>>>(W1, w1h, w1l, HID, 2 * HID);
    tsplit_kernel<<<dim3(HID / 32, 2 * HID / 32), dim3(32, 8)>>>(W2, w2h, w2l, 2 * HID, HID);

    // 3) tensorized edge message + scatter-add
    cudaFuncSetAttribute(edge_mma, cudaFuncAttributeMaxDynamicSharedMemorySize, EDGE_SMEM_BYTES);
    edge_mma<<<(E + 127) / 128, 256, EDGE_SMEM_BYTES>>>(x, ea, src, dst, weh, wel, be, aggr, E);

    // 4) GEMM1: h1 = ((1+eps)*x + aggr) @ W1 + b1, col stats
    cudaFuncSetAttribute(mma_gemm<1>, cudaFuncAttributeMaxDynamicSharedMemorySize, GEMM_SMEM_BYTES);
    cudaFuncSetAttribute(mma_gemm<2>, cudaFuncAttributeMaxDynamicSharedMemorySize, GEMM_SMEM_BYTES);
    {
        dim3 grid((2 * HID) / 128, (N + 127) / 128);
        mma_gemm<1><<<grid, 256, GEMM_SMEM_BYTES>>>(x, aggr, w1h, w1l, b1, nullptr, nullptr,
                                                    h1, stats1, N, HID, 2 * HID, epsp);
    }
    // 5) finalize BN1 params
    bnfin_kernel<<<(2 * HID + 255) / 256, 256>>>(stats1, g1, beta1, bnp1, 2 * HID, 1.0f / N);

    // 6) GEMM2 with fused BN1+SiLU prologue: h2 = silu(bn(h1)) @ W2 + b2, col stats
    {
        dim3 grid(HID / 128, (N + 127) / 128);
        mma_gemm<2><<<grid, 256, GEMM_SMEM_BYTES>>>(h1, nullptr, w2h, w2l, b2, bnp1, bnp1 + 2 * HID,
                                                    h2, stats2, N, 2 * HID, HID, epsp);
    }
    // 7) finalize BN2; final BN + SiLU into d_out
    bnfin_kernel<<<(HID + 255) / 256, 256>>>(stats2, g2, beta2, bnp2, HID, 1.0f / N);
    bnsilu_kernel<<<2048, 256>>>(h2, (float*)d_out, bnp2, 127, 128, (size_t)N * HID / 4);
}